// round 17
// baseline (speedup 1.0000x reference)
#include <cuda_runtime.h>
#include <math.h>

// Problem constants (fixed by setup_inputs)
#define B_   64
#define S_   256
#define H_   768
#define D_   64
#define NEG_ 4

#define EPSF 1e-15f
#define BNDF (1.0f - 1e-7f)
#define ATANH_BND 8.4056049f   // atanh(1 - 1e-7)

// Scratch (device globals — no allocation allowed)
__device__ float g_u [B_ * D_];
__device__ float g_v [B_ * D_];
__device__ float g_un[B_ * NEG_ * D_];

__device__ __forceinline__ float dot4(float4 a, float4 b) {
    return a.x * b.x + a.y * b.y + a.z * b.z + a.w * b.w;
}

// ---------------------------------------------------------------------------
// Stage 1: 96 blocks x 4 rows. float4 everywhere; expmap0 scale folded into
// the matvec read; artanh(tanh(n)) == n identity removes atanhf.
// ---------------------------------------------------------------------------
__global__ void __launch_bounds__(256, 4)
stage1_kernel(const float* __restrict__ enc,
              const float* __restrict__ nenc,
              const float* __restrict__ m1,
              const float* __restrict__ m2,
              const float* __restrict__ mneg,
              const float* __restrict__ Wm)
{
    const int base = blockIdx.x * 4;
    const int tid  = threadIdx.x;
    const int warp = tid >> 5;
    const int lane = tid & 31;

    __shared__ float4 s_p[4][H_ / 4];   // raw selected rows (192 float4 each)
    __shared__ float  s_mx[4][D_];
    __shared__ int    s_sel[4];
    __shared__ float  s_red[4][8];
    __shared__ float  s_es[4];          // expmap0 scale
    __shared__ float  s_xn[4];          // tanh(n)
    __shared__ float  s_nc[4];          // clamped norm (== artanh(xn))
    __shared__ float  s_ms[4];          // mobius scale

    const float* mask[4];
    const float* src[4];
    float*       dst[4];
    #pragma unroll
    for (int r = 0; r < 4; r++) {
        const int row = base + r;
        if (row < B_) {
            mask[r] = m1   + (size_t)row * S_;
            src[r]  = enc  + (size_t)row * S_ * H_;
            dst[r]  = g_u  + row * D_;
        } else if (row < 2 * B_) {
            const int q = row - B_;
            mask[r] = m2   + (size_t)q * S_;
            src[r]  = enc  + (size_t)q * S_ * H_;
            dst[r]  = g_v  + q * D_;
        } else {
            const int q = row - 2 * B_;
            mask[r] = mneg + (size_t)q * S_;
            src[r]  = nenc + (size_t)q * S_ * H_;
            dst[r]  = g_un + q * D_;
        }
    }

    // --- find one-hot indices ---
    #pragma unroll
    for (int r = 0; r < 4; r++)
        if (mask[r][tid] > 0.5f) s_sel[r] = tid;
    __syncthreads();

    // --- load selected rows (float4) + squared norms ---
    float acc[4] = {0.f, 0.f, 0.f, 0.f};
    if (tid < H_ / 4) {
        #pragma unroll
        for (int r = 0; r < 4; r++) {
            const float4* x4 = (const float4*)(src[r] + (size_t)s_sel[r] * H_);
            float4 v = __ldg(x4 + tid);
            s_p[r][tid] = v;
            acc[r] = dot4(v, v);
        }
    }
    #pragma unroll
    for (int o = 16; o; o >>= 1) {
        #pragma unroll
        for (int r = 0; r < 4; r++)
            acc[r] += __shfl_xor_sync(0xFFFFFFFFu, acc[r], o);
    }
    if (lane == 0) {
        #pragma unroll
        for (int r = 0; r < 4; r++) s_red[r][warp] = acc[r];
    }
    __syncthreads();
    if (tid < 4) {
        float n2 = 0.f;
        #pragma unroll
        for (int w = 0; w < 8; w++) n2 += s_red[tid][w];
        float n  = sqrtf(n2);
        float nc = fmaxf(n, EPSF);
        float t  = tanhf(nc);
        s_es[tid] = t / nc;                     // expmap0 scale
        s_xn[tid] = fmaxf(t, EPSF);             // xn = ||p|| (clamped)
        s_nc[tid] = fminf(nc, ATANH_BND);       // artanh(min(xn,BND)) == min(nc, atanh(BND))
    }
    __syncthreads();

    // --- mx[r] = (es_r * p_r) @ W^T : warp owns 8 W rows, float4 loads ---
    {
        const float es0 = s_es[0], es1 = s_es[1], es2 = s_es[2], es3 = s_es[3];
        float a[8][4];
        #pragma unroll
        for (int dd = 0; dd < 8; dd++)
            #pragma unroll
            for (int r = 0; r < 4; r++) a[dd][r] = 0.f;

        const float4* wbase = (const float4*)(Wm + (size_t)(warp * 8) * H_);
        #pragma unroll
        for (int i = 0; i < H_ / 128; i++) {          // 6 iterations
            const int k = lane + i * 32;
            float4 p0 = s_p[0][k], p1 = s_p[1][k];
            float4 p2 = s_p[2][k], p3 = s_p[3][k];
            p0.x *= es0; p0.y *= es0; p0.z *= es0; p0.w *= es0;
            p1.x *= es1; p1.y *= es1; p1.z *= es1; p1.w *= es1;
            p2.x *= es2; p2.y *= es2; p2.z *= es2; p2.w *= es2;
            p3.x *= es3; p3.y *= es3; p3.z *= es3; p3.w *= es3;
            #pragma unroll
            for (int dd = 0; dd < 8; dd++) {
                const float4 wv = __ldg(wbase + (size_t)dd * (H_ / 4) + k);
                a[dd][0] += dot4(p0, wv);
                a[dd][1] += dot4(p1, wv);
                a[dd][2] += dot4(p2, wv);
                a[dd][3] += dot4(p3, wv);
            }
        }
        #pragma unroll
        for (int o = 16; o; o >>= 1)
            #pragma unroll
            for (int dd = 0; dd < 8; dd++)
                #pragma unroll
                for (int r = 0; r < 4; r++)
                    a[dd][r] += __shfl_xor_sync(0xFFFFFFFFu, a[dd][r], o);
        if (lane == 0) {
            #pragma unroll
            for (int dd = 0; dd < 8; dd++)
                #pragma unroll
                for (int r = 0; r < 4; r++)
                    s_mx[r][warp * 8 + dd] = a[dd][r];
        }
    }
    __syncthreads();

    // --- mobius_matvec scale: tanh(mn/xn * nc) / mn ; warp r -> row r ---
    if (warp < 4) {
        float a0 = s_mx[warp][lane];
        float a1 = s_mx[warp][lane + 32];
        float a  = a0 * a0 + a1 * a1;
        #pragma unroll
        for (int o = 16; o; o >>= 1) a += __shfl_xor_sync(0xFFFFFFFFu, a, o);
        if (lane == 0) {
            float mn  = sqrtf(a);
            float mnc = fmaxf(mn, EPSF);
            s_ms[warp] = tanhf(mnc / s_xn[warp] * s_nc[warp]) / mnc;
        }
    }
    __syncthreads();

    // --- write: 256 threads = 4 rows x 64 dims ---
    {
        const int r = tid >> 6;
        const int d = tid & 63;
        dst[r][d] = s_ms[r] * s_mx[r][d];
    }
}

// ---------------------------------------------------------------------------
// Stage 2: 1 block x 1024 threads = 64 groups of 16 lanes, one row per group.
// exp(-2 atanh(z)) == (1-z)/(1+z): no atanhf, no expf — per row only
// 1 acosf + 1 logf remain.
// ---------------------------------------------------------------------------
__global__ void __launch_bounds__(1024, 1)
stage2_kernel(float* __restrict__ out)
{
    const int tid  = threadIdx.x;
    const int b    = tid >> 4;        // row 0..63
    const int l16  = tid & 15;        // lane within 16-group
    __shared__ float s_loss[B_];
    __shared__ float s_part[2];

    const float4* u4  = (const float4*)(g_u  + b * D_);
    const float4* v4  = (const float4*)(g_v  + b * D_);
    const float4* un4 = (const float4*)(g_un + (size_t)b * NEG_ * D_);

    const float4 uu = u4[l16];
    const float4 vv = v4[l16];
    const float4 w0 = un4[l16];
    const float4 w1 = un4[16 + l16];
    const float4 w2 = un4[32 + l16];
    const float4 w3 = un4[48 + l16];

    float x2 = dot4(uu, uu);
    float y2 = dot4(vv, vv);
    float xy = dot4(uu, vv);
    float n0 = dot4(w0, w0);
    float n1 = dot4(w1, w1);
    float n2 = dot4(w2, w2);
    float n3 = dot4(w3, w3);
    float c0 = dot4(uu, w0);
    float c1 = dot4(uu, w1);
    float c2 = dot4(uu, w2);
    float c3 = dot4(uu, w3);

    #pragma unroll
    for (int o = 8; o; o >>= 1) {
        x2 += __shfl_xor_sync(0xFFFFFFFFu, x2, o, 16);
        y2 += __shfl_xor_sync(0xFFFFFFFFu, y2, o, 16);
        xy += __shfl_xor_sync(0xFFFFFFFFu, xy, o, 16);
        n0 += __shfl_xor_sync(0xFFFFFFFFu, n0, o, 16);
        n1 += __shfl_xor_sync(0xFFFFFFFFu, n1, o, 16);
        n2 += __shfl_xor_sync(0xFFFFFFFFu, n2, o, 16);
        n3 += __shfl_xor_sync(0xFFFFFFFFu, n3, o, 16);
        c0 += __shfl_xor_sync(0xFFFFFFFFu, c0, o, 16);
        c1 += __shfl_xor_sync(0xFFFFFFFFu, c1, o, 16);
        c2 += __shfl_xor_sync(0xFFFFFFFFu, c2, o, 16);
        c3 += __shfl_xor_sync(0xFFFFFFFFu, c3, o, 16);
    }

    // Per-lane distance: lanes 0..3 -> negatives, lanes >=4 -> d(u,v).
    float A2, XY;
    if      (l16 == 0) { A2 = n0; XY = c0; }
    else if (l16 == 1) { A2 = n1; XY = c1; }
    else if (l16 == 2) { A2 = n2; XY = c2; }
    else if (l16 == 3) { A2 = n3; XY = c3; }
    else               { A2 = y2; XY = xy; }

    // ||mobius_add(-u, y)||^2 via dot-product algebra, then
    // e = exp(-2 atanh(z)) = (1 - z) / (1 + z).
    const float cA  = 1.0f - 2.0f * XY + A2;
    const float cB  = 1.0f - x2;
    const float den = fmaxf(1.0f - 2.0f * XY + x2 * A2, EPSF);
    float ms = cA * cA * x2 - 2.0f * cA * cB * XY + cB * cB * A2;
    ms = fmaxf(ms, 0.0f);
    const float z = fminf(sqrtf(ms) / den, BNDF);
    const float e = (1.0f - z) / (1.0f + z);

    const float Z1 = __shfl_sync(0xFFFFFFFFu, e, 0, 16)
                   + __shfl_sync(0xFFFFFFFFu, e, 1, 16)
                   + __shfl_sync(0xFFFFFFFFu, e, 2, 16)
                   + __shfl_sync(0xFFFFFFFFu, e, 3, 16);
    const float expneg = __shfl_sync(0xFFFFFFFFu, e, 4, 16);

    // angle (all lanes compute it; overlaps the distance chain)
    const float euclid = sqrtf(fmaxf(x2 + y2 - 2.0f * xy, 0.0f));
    const float rad    = fmaxf(1.0f + x2 * y2 - 2.0f * xy, EPSF);
    const float aden   = fmaxf(sqrtf(y2) * euclid * sqrtf(rad), EPSF);
    float cosang = (xy * (1.0f + y2) - y2 * (1.0f + x2)) / aden;
    cosang = fminf(fmaxf(cosang, -BNDF), BNDF);
    const float ang = acosf(cosang);

    const float nsl = -logf(expneg / (Z1 + expneg));
    if (l16 == 0) s_loss[b] = ang + nsl;   // 2(1-a)ang + 2a nsl, a = 0.5
    __syncthreads();

    if (tid < 64) {
        float l = s_loss[tid];
        #pragma unroll
        for (int o = 16; o; o >>= 1) l += __shfl_xor_sync(0xFFFFFFFFu, l, o);
        if ((tid & 31) == 0) s_part[tid >> 5] = l;
    }
    __syncthreads();
    if (tid == 0)
        out[0] = (s_part[0] + s_part[1]) * (1.0f / (float)B_);
}

// ---------------------------------------------------------------------------
extern "C" void kernel_launch(void* const* d_in, const int* in_sizes, int n_in,
                              void* d_out, int out_size)
{
    const float* enc  = (const float*)d_in[0];  // [64,256,768]
    const float* nenc = (const float*)d_in[1];  // [256,256,768]
    const float* m1   = (const float*)d_in[2];  // [64,256,1]
    const float* m2   = (const float*)d_in[3];  // [64,256,1]
    const float* mneg = (const float*)d_in[4];  // [256,256,1]
    const float* Wm   = (const float*)d_in[5];  // [64,768]
    float* out = (float*)d_out;

    stage1_kernel<<<(2 * B_ + B_ * NEG_) / 4, 256>>>(enc, nenc, m1, m2, mneg, Wm);
    stage2_kernel<<<1, 1024>>>(out);
}